// round 3
// baseline (speedup 1.0000x reference)
#include <cuda_runtime.h>
#include <cstdint>
#include <math.h>

// Problem dims (fixed by setup_inputs)
#define TT 50
#define BB 256
#define AA 64
#define SS 256
#define HH 1024
#define OO 1024

// ---------------- device scratch (static allocation only) ----------------
__device__ float g_noise[2 * TT * BB * SS];        // 26.2 MB, [2,T,B,S]
__device__ float g_belief[BB * HH];
__device__ float g_state[BB * SS];
__device__ float g_h1[BB * HH];
__device__ float g_xg[BB * 3 * HH];
__device__ float g_hg[BB * 3 * HH];
__device__ float g_p1[BB * HH];
__device__ float g_q1[BB * HH];
__device__ float g_ph[BB * 2 * SS];
__device__ float g_qh[BB * 2 * SS];

// ---------------- helpers ----------------
__device__ __forceinline__ unsigned long long pack2(float x, float y) {
    unsigned long long r;
    asm("mov.b64 %0, {%1, %2};" : "=l"(r) : "f"(x), "f"(y));
    return r;
}
__device__ __forceinline__ void unpack2(unsigned long long v, float& x, float& y) {
    asm("mov.b64 {%0, %1}, %2;" : "=f"(x), "=f"(y) : "l"(v));
}
__device__ __forceinline__ unsigned long long ffma2(unsigned long long a,
                                                    unsigned long long b,
                                                    unsigned long long c) {
    unsigned long long d;
    asm("fma.rn.f32x2 %0, %1, %2, %3;" : "=l"(d) : "l"(a), "l"(b), "l"(c));
    return d;
}

__device__ __forceinline__ float sigmoidf_(float x) { return 1.0f / (1.0f + expf(-x)); }
__device__ __forceinline__ float softplusf_(float x) {
    return fmaxf(x, 0.0f) + log1pf(expf(-fabsf(x)));
}

// ---------------- JAX threefry2x32 noise (key = (0,42)) ----------------
__device__ __forceinline__ uint32_t rotl32(uint32_t x, int r) {
    return (x << r) | (x >> (32 - r));
}

// XLA/Giles erfinv (f32), times sqrt(2)
__device__ __forceinline__ float normal_from_bits(uint32_t bits) {
    uint32_t fb = (bits >> 9) | 0x3f800000u;
    float f = __uint_as_float(fb) - 1.0f;              // [0,1)
    const float lo = -0.99999994f;                     // nextafter(-1,0)
    float u = f * 2.0f + lo;                           // (hi-lo) rounds to 2.0f
    u = fmaxf(lo, u);
    float w = -log1pf(-u * u);
    float p;
    if (w < 5.0f) {
        w -= 2.5f;
        p = 2.81022636e-08f;
        p = fmaf(p, w, 3.43273939e-07f);
        p = fmaf(p, w, -3.5233877e-06f);
        p = fmaf(p, w, -4.39150654e-06f);
        p = fmaf(p, w, 0.00021858087f);
        p = fmaf(p, w, -0.00125372503f);
        p = fmaf(p, w, -0.00417768164f);
        p = fmaf(p, w, 0.246640727f);
        p = fmaf(p, w, 1.50140941f);
    } else {
        w = sqrtf(w) - 3.0f;
        p = -0.000200214257f;
        p = fmaf(p, w, 0.000100950558f);
        p = fmaf(p, w, 0.00134934322f);
        p = fmaf(p, w, -0.00367342844f);
        p = fmaf(p, w, 0.00573950773f);
        p = fmaf(p, w, -0.0076224613f);
        p = fmaf(p, w, 0.00943887047f);
        p = fmaf(p, w, 1.00167406f);
        p = fmaf(p, w, 2.83297682f);
    }
    return 1.41421356f * (p * u);
}

// Partitionable threefry (jax_threefry_partitionable=True, default since 0.4.36):
// per element i: counter = (i>>32, i&0xffffffff) = (0, i);
// PRF emits (bits1, bits2); for 32-bit dtypes JAX returns bits1 ^ bits2.
__global__ void noise_kernel() {
    const int total = 2 * TT * BB * SS;  // 6,553,600
    int i = blockIdx.x * blockDim.x + threadIdx.x;
    if (i >= total) return;
    const uint32_t k0 = 0u, k1 = 42u;
    const uint32_t k2 = k0 ^ k1 ^ 0x1BD11BDAu;
    uint32_t x0 = 0u;                 // high 32 bits of 64-bit counter (always 0)
    uint32_t x1 = (uint32_t)i;        // low 32 bits
    x0 += k0; x1 += k1;
#define RND(r) { x0 += x1; x1 = rotl32(x1, r); x1 ^= x0; }
    RND(13) RND(15) RND(26) RND(6)   x0 += k1; x1 += k2 + 1u;
    RND(17) RND(29) RND(16) RND(24)  x0 += k2; x1 += k0 + 2u;
    RND(13) RND(15) RND(26) RND(6)   x0 += k0; x1 += k1 + 3u;
    RND(17) RND(29) RND(16) RND(24)  x0 += k1; x1 += k2 + 4u;
    RND(13) RND(15) RND(26) RND(6)   x0 += k2; x1 += k0 + 5u;
#undef RND
    g_noise[i] = normal_from_bits(x0 ^ x1);   // XOR of both PRF output lanes
}

__global__ void init_kernel(const float* __restrict__ prev_state,
                            const float* __restrict__ prev_belief) {
    int i = blockIdx.x * blockDim.x + threadIdx.x;  // up to 262144
    if (i < BB * SS) g_state[i] = prev_state[i];
    if (i < BB * HH) g_belief[i] = prev_belief[i];
}

// ---------------- fp32 GEMM via packed fma.rn.f32x2 ----------------
// C[M=256, N] = act( [A0 (K0 cols, rows scaled by rowscale) | A1 (K1 cols)] @ W + bias )
// W is row-major [K, N]. Grid: (N/128, 4), 256 threads, 64x128 tile, 4x8 microtile.
// K0 % 16 == 0 so every 16-wide K tile lies fully in A0 or A1.
__global__ __launch_bounds__(256) void gemm_kernel(
    const float* __restrict__ A0, int K0, const float* __restrict__ rowscale,
    const float* __restrict__ A1, int K1,
    const float* __restrict__ W, const float* __restrict__ bias,
    float* __restrict__ C, int N, int doRelu)
{
    __shared__ float As[16][64];    // [k][m]
    __shared__ float Ws[16][128];   // [k][n]
    const int t = threadIdx.x;
    const int tx = t & 15, ty = t >> 4;
    const int n0 = blockIdx.x * 128;
    const int m0 = blockIdx.y * 64;
    const int K = K0 + K1;

    unsigned long long acc[4][4];
#pragma unroll
    for (int i = 0; i < 4; ++i)
#pragma unroll
        for (int j = 0; j < 4; ++j) acc[i][j] = 0ull;

    for (int k0 = 0; k0 < K; k0 += 16) {
        // A tile: thread t loads float4 at (m = t/4, k4 = (t%4)*4)
        {
            int m = t >> 2;
            int k4 = (t & 3) << 2;
            int gm = m0 + m;
            int gk = k0 + k4;
            float4 v;
            if (gk < K0) {
                v = *(const float4*)(A0 + (size_t)gm * K0 + gk);
                if (rowscale) {
                    float s = rowscale[gm];
                    v.x *= s; v.y *= s; v.z *= s; v.w *= s;
                }
            } else {
                v = *(const float4*)(A1 + (size_t)gm * K1 + (gk - K0));
            }
            As[k4 + 0][m] = v.x; As[k4 + 1][m] = v.y;
            As[k4 + 2][m] = v.z; As[k4 + 3][m] = v.w;
        }
        // W tile: 16x128 floats = 512 float4, 2 per thread
        {
#pragma unroll
            for (int r = 0; r < 2; ++r) {
                int f = t + r * 256;
                int kk = f >> 5;
                int nf = (f & 31) << 2;
                *(float4*)&Ws[kk][nf] =
                    *(const float4*)(W + (size_t)(k0 + kk) * N + n0 + nf);
            }
        }
        __syncthreads();
#pragma unroll
        for (int kk = 0; kk < 16; ++kk) {
            float4 av = *(const float4*)(&As[kk][ty << 2]);
            unsigned long long ap[4];
            ap[0] = pack2(av.x, av.x);
            ap[1] = pack2(av.y, av.y);
            ap[2] = pack2(av.z, av.z);
            ap[3] = pack2(av.w, av.w);
            const unsigned long long* wr =
                (const unsigned long long*)(&Ws[kk][tx << 3]);
            unsigned long long wv[4];
#pragma unroll
            for (int j = 0; j < 4; ++j) wv[j] = wr[j];
#pragma unroll
            for (int i = 0; i < 4; ++i)
#pragma unroll
                for (int j = 0; j < 4; ++j)
                    acc[i][j] = ffma2(ap[i], wv[j], acc[i][j]);
        }
        __syncthreads();
    }

    const int nb = n0 + (tx << 3);
    const int mb = m0 + (ty << 2);
    float bs[8];
#pragma unroll
    for (int c = 0; c < 8; ++c) bs[c] = bias[nb + c];
#pragma unroll
    for (int i = 0; i < 4; ++i) {
        float o[8];
#pragma unroll
        for (int j = 0; j < 4; ++j) unpack2(acc[i][j], o[2 * j], o[2 * j + 1]);
#pragma unroll
        for (int c = 0; c < 8; ++c) {
            o[c] += bs[c];
            if (doRelu) o[c] = fmaxf(o[c], 0.0f);
        }
        float4* dst = (float4*)(C + (size_t)(mb + i) * N + nb);
        dst[0] = make_float4(o[0], o[1], o[2], o[3]);
        dst[1] = make_float4(o[4], o[5], o[6], o[7]);
    }
}

// ---------------- GRU elementwise (keras v2, reset_after) ----------------
__global__ void gru_kernel(float* __restrict__ out_belief_t) {
    int idx = blockIdx.x * blockDim.x + threadIdx.x;  // B*H = 262144
    int b = idx >> 10, j = idx & 1023;
    const float* xr_ = g_xg + (size_t)b * 3072;
    const float* hr_ = g_hg + (size_t)b * 3072;
    float z = sigmoidf_(xr_[j] + hr_[j]);
    float r = sigmoidf_(xr_[1024 + j] + hr_[1024 + j]);
    float cand = tanhf(xr_[2048 + j] + r * hr_[2048 + j]);
    float bo = g_belief[idx];
    float bn = z * bo + (1.0f - z) * cand;
    g_belief[idx] = bn;
    if (out_belief_t) out_belief_t[idx] = bn;
}

// ---------------- prior/posterior heads elementwise ----------------
__global__ void heads_kernel(const float* __restrict__ nP, const float* __restrict__ nQ,
                             float* __restrict__ o_prior, float* __restrict__ o_pm,
                             float* __restrict__ o_ps, float* __restrict__ o_post,
                             float* __restrict__ o_qm, float* __restrict__ o_qs) {
    int idx = blockIdx.x * blockDim.x + threadIdx.x;  // B*S = 65536
    int b = idx >> 8, s = idx & 255;
    float pm = g_ph[b * 512 + s];
    float ps = softplusf_(g_ph[b * 512 + 256 + s]) + 0.1f;
    float pr = pm + ps * nP[idx];
    float qm = g_qh[b * 512 + s];
    float qs = softplusf_(g_qh[b * 512 + 256 + s]) + 0.1f;
    float po = qm + qs * nQ[idx];
    if (o_pm)    { o_pm[idx] = pm; o_ps[idx] = ps; o_prior[idx] = pr;
                   o_qm[idx] = qm; o_qs[idx] = qs; o_post[idx] = po; }
    g_state[idx] = po;
}

// ---------------- launch ----------------
extern "C" void kernel_launch(void* const* d_in, const int* in_sizes, int n_in,
                              void* d_out, int out_size) {
    const float* actions      = (const float*)d_in[0];
    const float* prev_state   = (const float*)d_in[1];
    const float* prev_belief  = (const float*)d_in[2];
    const float* observations = (const float*)d_in[3];
    const float* nonterminals = (const float*)d_in[4];
    const float* W_sa = (const float*)d_in[5];
    const float* b_sa = (const float*)d_in[6];
    const float* W_x  = (const float*)d_in[7];
    const float* W_h  = (const float*)d_in[8];
    const float* b_x  = (const float*)d_in[9];
    const float* b_h  = (const float*)d_in[10];
    const float* W_bp = (const float*)d_in[11];
    const float* b_bp = (const float*)d_in[12];
    const float* W_sp = (const float*)d_in[13];
    const float* b_sp = (const float*)d_in[14];
    const float* W_bq = (const float*)d_in[15];
    const float* b_bq = (const float*)d_in[16];
    const float* W_sq = (const float*)d_in[17];
    const float* b_sq = (const float*)d_in[18];
    float* out = (float*)d_out;

    // output layout: concat of 7 stacked arrays
    const size_t O_BEL  = 0;                                  // [T,B,H]
    const size_t O_PRI  = (size_t)TT * BB * HH;               // 13,107,200
    const size_t O_PM   = O_PRI  + (size_t)TT * BB * SS;
    const size_t O_PS   = O_PM   + (size_t)TT * BB * SS;
    const size_t O_POST = O_PS   + (size_t)TT * BB * SS;
    const size_t O_QM   = O_POST + (size_t)TT * BB * SS;
    const size_t O_QS   = O_QM   + (size_t)TT * BB * SS;
    const size_t FULL   = O_QS   + (size_t)TT * BB * SS;      // 32,768,000

    const bool full = (size_t)out_size >= FULL;               // guard vs layout ambiguity

    float *nz, *bel, *st, *h1, *xg, *hg, *p1, *q1, *ph, *qh;
    cudaGetSymbolAddress((void**)&nz, g_noise);
    cudaGetSymbolAddress((void**)&bel, g_belief);
    cudaGetSymbolAddress((void**)&st, g_state);
    cudaGetSymbolAddress((void**)&h1, g_h1);
    cudaGetSymbolAddress((void**)&xg, g_xg);
    cudaGetSymbolAddress((void**)&hg, g_hg);
    cudaGetSymbolAddress((void**)&p1, g_p1);
    cudaGetSymbolAddress((void**)&q1, g_q1);
    cudaGetSymbolAddress((void**)&ph, g_ph);
    cudaGetSymbolAddress((void**)&qh, g_qh);

    noise_kernel<<<(2 * TT * BB * SS + 255) / 256, 256>>>();
    init_kernel<<<(BB * HH + 255) / 256, 256>>>(prev_state, prev_belief);

    for (int t = 0; t < TT; ++t) {
        const float* a_t  = actions + (size_t)t * BB * AA;
        const float* o_t  = observations + (size_t)t * BB * OO;
        const float* nt_t = nonterminals + (size_t)t * BB;

        // h1 = relu([state*nt, a] @ W_sa + b_sa)   [256,1024], K=320
        gemm_kernel<<<dim3(HH / 128, 4), 256>>>(st, SS, nt_t, a_t, AA,
                                                W_sa, b_sa, h1, HH, 1);
        // xg = h1 @ W_x + b_x ; hg = belief @ W_h + b_h   [256,3072], K=1024
        gemm_kernel<<<dim3(3 * HH / 128, 4), 256>>>(h1, HH, nullptr, nullptr, 0,
                                                    W_x, b_x, xg, 3 * HH, 0);
        gemm_kernel<<<dim3(3 * HH / 128, 4), 256>>>(bel, HH, nullptr, nullptr, 0,
                                                    W_h, b_h, hg, 3 * HH, 0);
        // GRU -> new belief (also stored to output)
        gru_kernel<<<(BB * HH) / 256, 256>>>(out + O_BEL + (size_t)t * BB * HH);
        // prior hidden / posterior hidden
        gemm_kernel<<<dim3(HH / 128, 4), 256>>>(bel, HH, nullptr, nullptr, 0,
                                                W_bp, b_bp, p1, HH, 1);
        gemm_kernel<<<dim3(HH / 128, 4), 256>>>(bel, HH, nullptr, o_t, OO,
                                                W_bq, b_bq, q1, HH, 1);
        // head projections [256,512], K=1024
        gemm_kernel<<<dim3(512 / 128, 4), 256>>>(p1, HH, nullptr, nullptr, 0,
                                                 W_sp, b_sp, ph, 512, 0);
        gemm_kernel<<<dim3(512 / 128, 4), 256>>>(q1, HH, nullptr, nullptr, 0,
                                                 W_sq, b_sq, qh, 512, 0);
        // sample prior/posterior, write 6 output slices + next state
        heads_kernel<<<(BB * SS) / 256, 256>>>(
            nz + (size_t)t * BB * SS, nz + (size_t)(TT + t) * BB * SS,
            full ? out + O_PRI  + (size_t)t * BB * SS : nullptr,
            full ? out + O_PM   + (size_t)t * BB * SS : nullptr,
            full ? out + O_PS   + (size_t)t * BB * SS : nullptr,
            full ? out + O_POST + (size_t)t * BB * SS : nullptr,
            full ? out + O_QM   + (size_t)t * BB * SS : nullptr,
            full ? out + O_QS   + (size_t)t * BB * SS : nullptr);
    }
}

// round 4
// speedup vs baseline: 1.2403x; 1.2403x over previous
#include <cuda_runtime.h>
#include <cstdint>
#include <math.h>

// Problem dims (fixed by setup_inputs)
#define TT 50
#define BB 256
#define AA 64
#define SS 256
#define HH 1024
#define OO 1024

// ---------------- device scratch (static allocation only) ----------------
__device__ float g_noise[2 * TT * BB * SS];        // 26.2 MB, [2,T,B,S]
__device__ float g_belief[BB * HH];
__device__ float g_state[BB * SS];
__device__ float g_h1[BB * HH];
__device__ float g_xg[BB * 3 * HH];
__device__ float g_hg[BB * 3 * HH];
__device__ float g_p1[BB * HH];
__device__ float g_q1[BB * HH];
__device__ float g_ph[BB * 2 * SS];
__device__ float g_qh[BB * 2 * SS];

// ---------------- helpers ----------------
__device__ __forceinline__ unsigned long long pack2(float x, float y) {
    unsigned long long r;
    asm("mov.b64 %0, {%1, %2};" : "=l"(r) : "f"(x), "f"(y));
    return r;
}
__device__ __forceinline__ void unpack2(unsigned long long v, float& x, float& y) {
    asm("mov.b64 {%0, %1}, %2;" : "=f"(x), "=f"(y) : "l"(v));
}
__device__ __forceinline__ unsigned long long ffma2(unsigned long long a,
                                                    unsigned long long b,
                                                    unsigned long long c) {
    unsigned long long d;
    asm("fma.rn.f32x2 %0, %1, %2, %3;" : "=l"(d) : "l"(a), "l"(b), "l"(c));
    return d;
}

__device__ __forceinline__ float sigmoidf_(float x) { return 1.0f / (1.0f + expf(-x)); }
__device__ __forceinline__ float softplusf_(float x) {
    return fmaxf(x, 0.0f) + log1pf(expf(-fabsf(x)));
}

// ---------------- JAX threefry2x32 noise (key = (0,42)) ----------------
__device__ __forceinline__ uint32_t rotl32(uint32_t x, int r) {
    return (x << r) | (x >> (32 - r));
}

// XLA/Giles erfinv (f32), times sqrt(2)
__device__ __forceinline__ float normal_from_bits(uint32_t bits) {
    uint32_t fb = (bits >> 9) | 0x3f800000u;
    float f = __uint_as_float(fb) - 1.0f;              // [0,1)
    const float lo = -0.99999994f;                     // nextafter(-1,0)
    float u = f * 2.0f + lo;                           // (hi-lo) rounds to 2.0f
    u = fmaxf(lo, u);
    float w = -log1pf(-u * u);
    float p;
    if (w < 5.0f) {
        w -= 2.5f;
        p = 2.81022636e-08f;
        p = fmaf(p, w, 3.43273939e-07f);
        p = fmaf(p, w, -3.5233877e-06f);
        p = fmaf(p, w, -4.39150654e-06f);
        p = fmaf(p, w, 0.00021858087f);
        p = fmaf(p, w, -0.00125372503f);
        p = fmaf(p, w, -0.00417768164f);
        p = fmaf(p, w, 0.246640727f);
        p = fmaf(p, w, 1.50140941f);
    } else {
        w = sqrtf(w) - 3.0f;
        p = -0.000200214257f;
        p = fmaf(p, w, 0.000100950558f);
        p = fmaf(p, w, 0.00134934322f);
        p = fmaf(p, w, -0.00367342844f);
        p = fmaf(p, w, 0.00573950773f);
        p = fmaf(p, w, -0.0076224613f);
        p = fmaf(p, w, 0.00943887047f);
        p = fmaf(p, w, 1.00167406f);
        p = fmaf(p, w, 2.83297682f);
    }
    return 1.41421356f * (p * u);
}

// Partitionable threefry: counter (0, i), result = bits1 ^ bits2.
__global__ void noise_kernel() {
    const int total = 2 * TT * BB * SS;  // 6,553,600
    int i = blockIdx.x * blockDim.x + threadIdx.x;
    if (i >= total) return;
    const uint32_t k0 = 0u, k1 = 42u;
    const uint32_t k2 = k0 ^ k1 ^ 0x1BD11BDAu;
    uint32_t x0 = 0u;
    uint32_t x1 = (uint32_t)i;
    x0 += k0; x1 += k1;
#define RND(r) { x0 += x1; x1 = rotl32(x1, r); x1 ^= x0; }
    RND(13) RND(15) RND(26) RND(6)   x0 += k1; x1 += k2 + 1u;
    RND(17) RND(29) RND(16) RND(24)  x0 += k2; x1 += k0 + 2u;
    RND(13) RND(15) RND(26) RND(6)   x0 += k0; x1 += k1 + 3u;
    RND(17) RND(29) RND(16) RND(24)  x0 += k1; x1 += k2 + 4u;
    RND(13) RND(15) RND(26) RND(6)   x0 += k2; x1 += k0 + 5u;
#undef RND
    g_noise[i] = normal_from_bits(x0 ^ x1);
}

__global__ void init_kernel(const float* __restrict__ prev_state,
                            const float* __restrict__ prev_belief) {
    int i = blockIdx.x * blockDim.x + threadIdx.x;
    if (i < BB * SS) g_state[i] = prev_state[i];
    if (i < BB * HH) g_belief[i] = prev_belief[i];
}

// ---------------- batched fp32 GEMM (FFMA2), 32x128 tile ----------------
struct GemmOp {
    const float* A0; int K0;
    const float* rowscale;          // optional per-row scale on A0 (nonterminals)
    const float* A1; int K1;        // optional concat block
    const float* W;                 // [K, N] row-major
    const float* bias;              // [N]
    float* C;                       // [256, N]
    int N;
    int doRelu;
};

// grid: (N/128, 256/32, nOps), 256 threads. Each thread: 2 rows x 8 cols.
__global__ __launch_bounds__(256) void gemm_kernel(GemmOp op0, GemmOp op1) {
    const GemmOp op = blockIdx.z ? op1 : op0;
    __shared__ float As[32][33];    // [k][m], padded: conflict-free
    __shared__ float Ws[32][128];   // [k][n]
    const int t = threadIdx.x;
    const int tx = t & 15;          // 16 col groups x 8
    const int ty = t >> 4;          // 16 row groups x 2
    const int n0 = blockIdx.x * 128;
    const int m0 = blockIdx.y * 32;
    const int K = op.K0 + op.K1;

    unsigned long long acc[2][4];
#pragma unroll
    for (int i = 0; i < 2; ++i)
#pragma unroll
        for (int j = 0; j < 4; ++j) acc[i][j] = 0ull;

    const int am = t >> 3;          // 0..31 (row within tile)
    const int ak = (t & 7) << 2;    // 0,4,...,28 (k within tile)
    const int gm = m0 + am;
    const float rs = op.rowscale ? op.rowscale[gm] : 1.0f;

    for (int k0 = 0; k0 < K; k0 += 32) {
        // A tile: one float4 per thread (K0, K1 are multiples of 4)
        {
            int gk = k0 + ak;
            float4 v;
            if (gk < op.K0) {
                v = *(const float4*)(op.A0 + (size_t)gm * op.K0 + gk);
                v.x *= rs; v.y *= rs; v.z *= rs; v.w *= rs;
            } else {
                v = *(const float4*)(op.A1 + (size_t)gm * op.K1 + (gk - op.K0));
            }
            As[ak + 0][am] = v.x; As[ak + 1][am] = v.y;
            As[ak + 2][am] = v.z; As[ak + 3][am] = v.w;
        }
        // W tile: 32x128 = 1024 float4, 4 per thread
        {
#pragma unroll
            for (int r = 0; r < 4; ++r) {
                int f = t + r * 256;
                int kk = f >> 5;
                int nf = (f & 31) << 2;
                *(float4*)&Ws[kk][nf] =
                    *(const float4*)(op.W + (size_t)(k0 + kk) * op.N + n0 + nf);
            }
        }
        __syncthreads();
#pragma unroll
        for (int kk = 0; kk < 32; ++kk) {
            float a0 = As[kk][(ty << 1) + 0];
            float a1 = As[kk][(ty << 1) + 1];
            unsigned long long ap0 = pack2(a0, a0);
            unsigned long long ap1 = pack2(a1, a1);
            const unsigned long long* wr =
                (const unsigned long long*)(&Ws[kk][tx << 3]);
            unsigned long long w0 = wr[0], w1 = wr[1], w2 = wr[2], w3 = wr[3];
            acc[0][0] = ffma2(ap0, w0, acc[0][0]);
            acc[0][1] = ffma2(ap0, w1, acc[0][1]);
            acc[0][2] = ffma2(ap0, w2, acc[0][2]);
            acc[0][3] = ffma2(ap0, w3, acc[0][3]);
            acc[1][0] = ffma2(ap1, w0, acc[1][0]);
            acc[1][1] = ffma2(ap1, w1, acc[1][1]);
            acc[1][2] = ffma2(ap1, w2, acc[1][2]);
            acc[1][3] = ffma2(ap1, w3, acc[1][3]);
        }
        __syncthreads();
    }

    const int nb = n0 + (tx << 3);
    const int mb = m0 + (ty << 1);
    float bs[8];
#pragma unroll
    for (int c = 0; c < 8; ++c) bs[c] = op.bias[nb + c];
#pragma unroll
    for (int i = 0; i < 2; ++i) {
        float o[8];
#pragma unroll
        for (int j = 0; j < 4; ++j) unpack2(acc[i][j], o[2 * j], o[2 * j + 1]);
#pragma unroll
        for (int c = 0; c < 8; ++c) {
            o[c] += bs[c];
            if (op.doRelu) o[c] = fmaxf(o[c], 0.0f);
        }
        float4* dst = (float4*)(op.C + (size_t)(mb + i) * op.N + nb);
        dst[0] = make_float4(o[0], o[1], o[2], o[3]);
        dst[1] = make_float4(o[4], o[5], o[6], o[7]);
    }
}

// ---------------- GRU elementwise (keras v2, reset_after) ----------------
__global__ void gru_kernel(float* __restrict__ out_belief_t) {
    int idx = blockIdx.x * blockDim.x + threadIdx.x;  // B*H = 262144
    int b = idx >> 10, j = idx & 1023;
    const float* xr_ = g_xg + (size_t)b * 3072;
    const float* hr_ = g_hg + (size_t)b * 3072;
    float z = sigmoidf_(xr_[j] + hr_[j]);
    float r = sigmoidf_(xr_[1024 + j] + hr_[1024 + j]);
    float cand = tanhf(xr_[2048 + j] + r * hr_[2048 + j]);
    float bo = g_belief[idx];
    float bn = z * bo + (1.0f - z) * cand;
    g_belief[idx] = bn;
    if (out_belief_t) out_belief_t[idx] = bn;
}

// ---------------- prior/posterior heads elementwise ----------------
__global__ void heads_kernel(const float* __restrict__ nP, const float* __restrict__ nQ,
                             float* __restrict__ o_prior, float* __restrict__ o_pm,
                             float* __restrict__ o_ps, float* __restrict__ o_post,
                             float* __restrict__ o_qm, float* __restrict__ o_qs) {
    int idx = blockIdx.x * blockDim.x + threadIdx.x;  // B*S = 65536
    int b = idx >> 8, s = idx & 255;
    float pm = g_ph[b * 512 + s];
    float ps = softplusf_(g_ph[b * 512 + 256 + s]) + 0.1f;
    float pr = pm + ps * nP[idx];
    float qm = g_qh[b * 512 + s];
    float qs = softplusf_(g_qh[b * 512 + 256 + s]) + 0.1f;
    float po = qm + qs * nQ[idx];
    if (o_pm)    { o_pm[idx] = pm; o_ps[idx] = ps; o_prior[idx] = pr;
                   o_qm[idx] = qm; o_qs[idx] = qs; o_post[idx] = po; }
    g_state[idx] = po;
}

// ---------------- launch ----------------
extern "C" void kernel_launch(void* const* d_in, const int* in_sizes, int n_in,
                              void* d_out, int out_size) {
    const float* actions      = (const float*)d_in[0];
    const float* prev_state   = (const float*)d_in[1];
    const float* prev_belief  = (const float*)d_in[2];
    const float* observations = (const float*)d_in[3];
    const float* nonterminals = (const float*)d_in[4];
    const float* W_sa = (const float*)d_in[5];
    const float* b_sa = (const float*)d_in[6];
    const float* W_x  = (const float*)d_in[7];
    const float* W_h  = (const float*)d_in[8];
    const float* b_x  = (const float*)d_in[9];
    const float* b_h  = (const float*)d_in[10];
    const float* W_bp = (const float*)d_in[11];
    const float* b_bp = (const float*)d_in[12];
    const float* W_sp = (const float*)d_in[13];
    const float* b_sp = (const float*)d_in[14];
    const float* W_bq = (const float*)d_in[15];
    const float* b_bq = (const float*)d_in[16];
    const float* W_sq = (const float*)d_in[17];
    const float* b_sq = (const float*)d_in[18];
    float* out = (float*)d_out;

    // output layout: concat of 7 stacked arrays
    const size_t O_BEL  = 0;
    const size_t O_PRI  = (size_t)TT * BB * HH;
    const size_t O_PM   = O_PRI  + (size_t)TT * BB * SS;
    const size_t O_PS   = O_PM   + (size_t)TT * BB * SS;
    const size_t O_POST = O_PS   + (size_t)TT * BB * SS;
    const size_t O_QM   = O_POST + (size_t)TT * BB * SS;
    const size_t O_QS   = O_QM   + (size_t)TT * BB * SS;
    const size_t FULL   = O_QS   + (size_t)TT * BB * SS;

    const bool full = (size_t)out_size >= FULL;

    float *nz, *bel, *st, *h1, *xg, *hg, *p1, *q1, *ph, *qh;
    cudaGetSymbolAddress((void**)&nz, g_noise);
    cudaGetSymbolAddress((void**)&bel, g_belief);
    cudaGetSymbolAddress((void**)&st, g_state);
    cudaGetSymbolAddress((void**)&h1, g_h1);
    cudaGetSymbolAddress((void**)&xg, g_xg);
    cudaGetSymbolAddress((void**)&hg, g_hg);
    cudaGetSymbolAddress((void**)&p1, g_p1);
    cudaGetSymbolAddress((void**)&q1, g_q1);
    cudaGetSymbolAddress((void**)&ph, g_ph);
    cudaGetSymbolAddress((void**)&qh, g_qh);

    noise_kernel<<<(2 * TT * BB * SS + 255) / 256, 256>>>();
    init_kernel<<<(BB * HH + 255) / 256, 256>>>(prev_state, prev_belief);

    for (int t = 0; t < TT; ++t) {
        const float* a_t  = actions + (size_t)t * BB * AA;
        const float* o_t  = observations + (size_t)t * BB * OO;
        const float* nt_t = nonterminals + (size_t)t * BB;

        // h1 = relu([state*nt, a] @ W_sa + b_sa)  [256,1024], K=320
        {
            GemmOp op{st, SS, nt_t, a_t, AA, W_sa, b_sa, h1, HH, 1};
            gemm_kernel<<<dim3(HH / 128, 8, 1), 256>>>(op, op);
        }
        // xg = h1 @ W_x + b_x ; hg = belief @ W_h + b_h  [256,3072] each, batched
        {
            GemmOp oa{h1,  HH, nullptr, nullptr, 0, W_x, b_x, xg, 3 * HH, 0};
            GemmOp ob{bel, HH, nullptr, nullptr, 0, W_h, b_h, hg, 3 * HH, 0};
            gemm_kernel<<<dim3(3 * HH / 128, 8, 2), 256>>>(oa, ob);
        }
        // GRU -> new belief
        gru_kernel<<<(BB * HH) / 256, 256>>>(out + O_BEL + (size_t)t * BB * HH);
        // p1 = relu(bel @ W_bp) ; q1 = relu([bel, o] @ W_bq)  batched
        {
            GemmOp oa{bel, HH, nullptr, nullptr, 0, W_bp, b_bp, p1, HH, 1};
            GemmOp ob{bel, HH, nullptr, o_t,    OO, W_bq, b_bq, q1, HH, 1};
            gemm_kernel<<<dim3(HH / 128, 8, 2), 256>>>(oa, ob);
        }
        // ph = p1 @ W_sp ; qh = q1 @ W_sq  [256,512] each, batched
        {
            GemmOp oa{p1, HH, nullptr, nullptr, 0, W_sp, b_sp, ph, 2 * SS, 0};
            GemmOp ob{q1, HH, nullptr, nullptr, 0, W_sq, b_sq, qh, 2 * SS, 0};
            gemm_kernel<<<dim3(2 * SS / 128, 8, 2), 256>>>(oa, ob);
        }
        // sample prior/posterior, write 6 output slices + next state
        heads_kernel<<<(BB * SS) / 256, 256>>>(
            nz + (size_t)t * BB * SS, nz + (size_t)(TT + t) * BB * SS,
            full ? out + O_PRI  + (size_t)t * BB * SS : nullptr,
            full ? out + O_PM   + (size_t)t * BB * SS : nullptr,
            full ? out + O_PS   + (size_t)t * BB * SS : nullptr,
            full ? out + O_POST + (size_t)t * BB * SS : nullptr,
            full ? out + O_QM   + (size_t)t * BB * SS : nullptr,
            full ? out + O_QS   + (size_t)t * BB * SS : nullptr);
    }
}

// round 5
// speedup vs baseline: 1.4535x; 1.1719x over previous
#include <cuda_runtime.h>
#include <cstdint>
#include <math.h>

// Problem dims (fixed by setup_inputs)
#define TT 50
#define BB 256
#define AA 64
#define SS 256
#define HH 1024
#define OO 1024

// ---------------- device scratch (static allocation only) ----------------
__device__ float g_noise[2 * TT * BB * SS];        // 26.2 MB, [2,T,B,S]
__device__ float g_belief[BB * HH];
__device__ float g_state[BB * SS];
__device__ float g_h1[BB * HH];
__device__ float g_xg[BB * 3 * HH];
__device__ float g_hg[BB * 3 * HH];
__device__ float g_p1[BB * HH];
__device__ float g_q1[BB * HH];
__device__ float g_ph[BB * 2 * SS];
__device__ float g_qh[BB * 2 * SS];

// ---------------- helpers ----------------
__device__ __forceinline__ unsigned long long pack2(float x, float y) {
    unsigned long long r;
    asm("mov.b64 %0, {%1, %2};" : "=l"(r) : "f"(x), "f"(y));
    return r;
}
__device__ __forceinline__ void unpack2(unsigned long long v, float& x, float& y) {
    asm("mov.b64 {%0, %1}, %2;" : "=f"(x), "=f"(y) : "l"(v));
}
__device__ __forceinline__ unsigned long long ffma2(unsigned long long a,
                                                    unsigned long long b,
                                                    unsigned long long c) {
    unsigned long long d;
    asm("fma.rn.f32x2 %0, %1, %2, %3;" : "=l"(d) : "l"(a), "l"(b), "l"(c));
    return d;
}

__device__ __forceinline__ float sigmoidf_(float x) { return 1.0f / (1.0f + expf(-x)); }
__device__ __forceinline__ float softplusf_(float x) {
    return fmaxf(x, 0.0f) + log1pf(expf(-fabsf(x)));
}

// ---------------- JAX threefry2x32 noise (key = (0,42)) ----------------
__device__ __forceinline__ uint32_t rotl32(uint32_t x, int r) {
    return (x << r) | (x >> (32 - r));
}

// XLA/Giles erfinv (f32), times sqrt(2)
__device__ __forceinline__ float normal_from_bits(uint32_t bits) {
    uint32_t fb = (bits >> 9) | 0x3f800000u;
    float f = __uint_as_float(fb) - 1.0f;              // [0,1)
    const float lo = -0.99999994f;                     // nextafter(-1,0)
    float u = f * 2.0f + lo;
    u = fmaxf(lo, u);
    float w = -log1pf(-u * u);
    float p;
    if (w < 5.0f) {
        w -= 2.5f;
        p = 2.81022636e-08f;
        p = fmaf(p, w, 3.43273939e-07f);
        p = fmaf(p, w, -3.5233877e-06f);
        p = fmaf(p, w, -4.39150654e-06f);
        p = fmaf(p, w, 0.00021858087f);
        p = fmaf(p, w, -0.00125372503f);
        p = fmaf(p, w, -0.00417768164f);
        p = fmaf(p, w, 0.246640727f);
        p = fmaf(p, w, 1.50140941f);
    } else {
        w = sqrtf(w) - 3.0f;
        p = -0.000200214257f;
        p = fmaf(p, w, 0.000100950558f);
        p = fmaf(p, w, 0.00134934322f);
        p = fmaf(p, w, -0.00367342844f);
        p = fmaf(p, w, 0.00573950773f);
        p = fmaf(p, w, -0.0076224613f);
        p = fmaf(p, w, 0.00943887047f);
        p = fmaf(p, w, 1.00167406f);
        p = fmaf(p, w, 2.83297682f);
    }
    return 1.41421356f * (p * u);
}

// Partitionable threefry: counter (0, i), result = bits1 ^ bits2.
__global__ void noise_kernel() {
    const int total = 2 * TT * BB * SS;  // 6,553,600
    int i = blockIdx.x * blockDim.x + threadIdx.x;
    if (i >= total) return;
    const uint32_t k0 = 0u, k1 = 42u;
    const uint32_t k2 = k0 ^ k1 ^ 0x1BD11BDAu;
    uint32_t x0 = 0u;
    uint32_t x1 = (uint32_t)i;
    x0 += k0; x1 += k1;
#define RND(r) { x0 += x1; x1 = rotl32(x1, r); x1 ^= x0; }
    RND(13) RND(15) RND(26) RND(6)   x0 += k1; x1 += k2 + 1u;
    RND(17) RND(29) RND(16) RND(24)  x0 += k2; x1 += k0 + 2u;
    RND(13) RND(15) RND(26) RND(6)   x0 += k0; x1 += k1 + 3u;
    RND(17) RND(29) RND(16) RND(24)  x0 += k1; x1 += k2 + 4u;
    RND(13) RND(15) RND(26) RND(6)   x0 += k2; x1 += k0 + 5u;
#undef RND
    g_noise[i] = normal_from_bits(x0 ^ x1);
}

__global__ void init_kernel(const float* __restrict__ prev_state,
                            const float* __restrict__ prev_belief) {
    int i = blockIdx.x * blockDim.x + threadIdx.x;
    if (i < BB * SS) g_state[i] = prev_state[i];
    if (i < BB * HH) g_belief[i] = prev_belief[i];
}

// ---------------- batched fp32 GEMM (FFMA2), 64x128 tile, double-buffered ----
struct GemmOp {
    const float* A0; int K0;
    const float* rowscale;          // optional per-row scale on A0 (nonterminals)
    const float* A1; int K1;        // optional concat block
    const float* W;                 // [K, N] row-major
    const float* bias;              // [N]
    float* C;                       // [256, N]
    int N;
    int doRelu;
};

// grid: (N/128, 256/64, nOps), 256 threads. Microtile 4 rows x 8 cols.
__global__ __launch_bounds__(256) void gemm_kernel(GemmOp op0, GemmOp op1) {
    const GemmOp op = blockIdx.z ? op1 : op0;
    __shared__ float As[2][16][64];     // [buf][k][m]
    __shared__ float Ws[2][16][128];    // [buf][k][n]
    const int t = threadIdx.x;
    const int tx = t & 15, ty = t >> 4;
    const int n0 = blockIdx.x * 128;
    const int m0 = blockIdx.y * 64;
    const int K = op.K0 + op.K1;
    const int nchunks = K >> 4;

    // A staging: thread loads float4 at (m = t>>2, k4 = (t&3)*4)
    const int am = t >> 2;              // 0..63
    const int ak = (t & 3) << 2;        // 0,4,8,12
    const int gm = m0 + am;
    const float rs = op.rowscale ? op.rowscale[gm] : 1.0f;
    // W staging: 2 float4 per thread
    const int wk0 = t >> 5;             // f = t: kk = t/32
    const int wn0 = (t & 31) << 2;
    const int wk1 = (t + 256) >> 5;
    const int wn1 = wn0;

    unsigned long long acc[4][4];
#pragma unroll
    for (int i = 0; i < 4; ++i)
#pragma unroll
        for (int j = 0; j < 4; ++j) acc[i][j] = 0ull;

    float4 aReg, wReg0, wReg1;

    auto load_regs = [&](int c) {
        int gk = (c << 4) + ak;
        if (gk < op.K0) {
            aReg = *(const float4*)(op.A0 + (size_t)gm * op.K0 + gk);
            aReg.x *= rs; aReg.y *= rs; aReg.z *= rs; aReg.w *= rs;
        } else {
            aReg = *(const float4*)(op.A1 + (size_t)gm * op.K1 + (gk - op.K0));
        }
        const float* wbase = op.W + (size_t)(c << 4) * op.N + n0;
        wReg0 = *(const float4*)(wbase + (size_t)wk0 * op.N + wn0);
        wReg1 = *(const float4*)(wbase + (size_t)wk1 * op.N + wn1);
    };
    auto sts = [&](int b) {
        As[b][ak + 0][am] = aReg.x;
        As[b][ak + 1][am] = aReg.y;
        As[b][ak + 2][am] = aReg.z;
        As[b][ak + 3][am] = aReg.w;
        *(float4*)&Ws[b][wk0][wn0] = wReg0;
        *(float4*)&Ws[b][wk1][wn1] = wReg1;
    };

    load_regs(0);
    sts(0);
    __syncthreads();

    int buf = 0;
    for (int c = 0; c < nchunks; ++c) {
        const bool has_next = (c + 1 < nchunks);
        if (has_next) load_regs(c + 1);
#pragma unroll
        for (int kk = 0; kk < 16; ++kk) {
            float4 av = *(const float4*)(&As[buf][kk][ty << 2]);
            unsigned long long ap0 = pack2(av.x, av.x);
            unsigned long long ap1 = pack2(av.y, av.y);
            unsigned long long ap2 = pack2(av.z, av.z);
            unsigned long long ap3 = pack2(av.w, av.w);
            const unsigned long long* wr =
                (const unsigned long long*)(&Ws[buf][kk][tx << 3]);
            unsigned long long w0 = wr[0], w1 = wr[1], w2 = wr[2], w3 = wr[3];
            acc[0][0] = ffma2(ap0, w0, acc[0][0]);
            acc[0][1] = ffma2(ap0, w1, acc[0][1]);
            acc[0][2] = ffma2(ap0, w2, acc[0][2]);
            acc[0][3] = ffma2(ap0, w3, acc[0][3]);
            acc[1][0] = ffma2(ap1, w0, acc[1][0]);
            acc[1][1] = ffma2(ap1, w1, acc[1][1]);
            acc[1][2] = ffma2(ap1, w2, acc[1][2]);
            acc[1][3] = ffma2(ap1, w3, acc[1][3]);
            acc[2][0] = ffma2(ap2, w0, acc[2][0]);
            acc[2][1] = ffma2(ap2, w1, acc[2][1]);
            acc[2][2] = ffma2(ap2, w2, acc[2][2]);
            acc[2][3] = ffma2(ap2, w3, acc[2][3]);
            acc[3][0] = ffma2(ap3, w0, acc[3][0]);
            acc[3][1] = ffma2(ap3, w1, acc[3][1]);
            acc[3][2] = ffma2(ap3, w2, acc[3][2]);
            acc[3][3] = ffma2(ap3, w3, acc[3][3]);
        }
        if (has_next) {
            sts(buf ^ 1);
            __syncthreads();
            buf ^= 1;
        }
    }

    const int nb = n0 + (tx << 3);
    const int mb = m0 + (ty << 2);
    float bs[8];
#pragma unroll
    for (int c = 0; c < 8; ++c) bs[c] = op.bias[nb + c];
#pragma unroll
    for (int i = 0; i < 4; ++i) {
        float o[8];
#pragma unroll
        for (int j = 0; j < 4; ++j) unpack2(acc[i][j], o[2 * j], o[2 * j + 1]);
#pragma unroll
        for (int c = 0; c < 8; ++c) {
            o[c] += bs[c];
            if (op.doRelu) o[c] = fmaxf(o[c], 0.0f);
        }
        float4* dst = (float4*)(op.C + (size_t)(mb + i) * op.N + nb);
        dst[0] = make_float4(o[0], o[1], o[2], o[3]);
        dst[1] = make_float4(o[4], o[5], o[6], o[7]);
    }
}

// ---------------- GRU elementwise (keras v2, reset_after) ----------------
__global__ void gru_kernel(float* __restrict__ out_belief_t) {
    int idx = blockIdx.x * blockDim.x + threadIdx.x;  // B*H = 262144
    int b = idx >> 10, j = idx & 1023;
    const float* xr_ = g_xg + (size_t)b * 3072;
    const float* hr_ = g_hg + (size_t)b * 3072;
    float z = sigmoidf_(xr_[j] + hr_[j]);
    float r = sigmoidf_(xr_[1024 + j] + hr_[1024 + j]);
    float cand = tanhf(xr_[2048 + j] + r * hr_[2048 + j]);
    float bo = g_belief[idx];
    float bn = z * bo + (1.0f - z) * cand;
    g_belief[idx] = bn;
    if (out_belief_t) out_belief_t[idx] = bn;
}

// ---------------- prior/posterior heads elementwise ----------------
__global__ void heads_kernel(const float* __restrict__ nP, const float* __restrict__ nQ,
                             float* __restrict__ o_prior, float* __restrict__ o_pm,
                             float* __restrict__ o_ps, float* __restrict__ o_post,
                             float* __restrict__ o_qm, float* __restrict__ o_qs) {
    int idx = blockIdx.x * blockDim.x + threadIdx.x;  // B*S = 65536
    int b = idx >> 8, s = idx & 255;
    float pm = g_ph[b * 512 + s];
    float ps = softplusf_(g_ph[b * 512 + 256 + s]) + 0.1f;
    float pr = pm + ps * nP[idx];
    float qm = g_qh[b * 512 + s];
    float qs = softplusf_(g_qh[b * 512 + 256 + s]) + 0.1f;
    float po = qm + qs * nQ[idx];
    if (o_pm)    { o_pm[idx] = pm; o_ps[idx] = ps; o_prior[idx] = pr;
                   o_qm[idx] = qm; o_qs[idx] = qs; o_post[idx] = po; }
    g_state[idx] = po;
}

// ---------------- launch ----------------
extern "C" void kernel_launch(void* const* d_in, const int* in_sizes, int n_in,
                              void* d_out, int out_size) {
    const float* actions      = (const float*)d_in[0];
    const float* prev_state   = (const float*)d_in[1];
    const float* prev_belief  = (const float*)d_in[2];
    const float* observations = (const float*)d_in[3];
    const float* nonterminals = (const float*)d_in[4];
    const float* W_sa = (const float*)d_in[5];
    const float* b_sa = (const float*)d_in[6];
    const float* W_x  = (const float*)d_in[7];
    const float* W_h  = (const float*)d_in[8];
    const float* b_x  = (const float*)d_in[9];
    const float* b_h  = (const float*)d_in[10];
    const float* W_bp = (const float*)d_in[11];
    const float* b_bp = (const float*)d_in[12];
    const float* W_sp = (const float*)d_in[13];
    const float* b_sp = (const float*)d_in[14];
    const float* W_bq = (const float*)d_in[15];
    const float* b_bq = (const float*)d_in[16];
    const float* W_sq = (const float*)d_in[17];
    const float* b_sq = (const float*)d_in[18];
    float* out = (float*)d_out;

    const size_t O_BEL  = 0;
    const size_t O_PRI  = (size_t)TT * BB * HH;
    const size_t O_PM   = O_PRI  + (size_t)TT * BB * SS;
    const size_t O_PS   = O_PM   + (size_t)TT * BB * SS;
    const size_t O_POST = O_PS   + (size_t)TT * BB * SS;
    const size_t O_QM   = O_POST + (size_t)TT * BB * SS;
    const size_t O_QS   = O_QM   + (size_t)TT * BB * SS;
    const size_t FULL   = O_QS   + (size_t)TT * BB * SS;

    const bool full = (size_t)out_size >= FULL;

    float *nz, *bel, *st, *h1, *xg, *hg, *p1, *q1, *ph, *qh;
    cudaGetSymbolAddress((void**)&nz, g_noise);
    cudaGetSymbolAddress((void**)&bel, g_belief);
    cudaGetSymbolAddress((void**)&st, g_state);
    cudaGetSymbolAddress((void**)&h1, g_h1);
    cudaGetSymbolAddress((void**)&xg, g_xg);
    cudaGetSymbolAddress((void**)&hg, g_hg);
    cudaGetSymbolAddress((void**)&p1, g_p1);
    cudaGetSymbolAddress((void**)&q1, g_q1);
    cudaGetSymbolAddress((void**)&ph, g_ph);
    cudaGetSymbolAddress((void**)&qh, g_qh);

    noise_kernel<<<(2 * TT * BB * SS + 255) / 256, 256>>>();
    init_kernel<<<(BB * HH + 255) / 256, 256>>>(prev_state, prev_belief);

    for (int t = 0; t < TT; ++t) {
        const float* a_t  = actions + (size_t)t * BB * AA;
        const float* o_t  = observations + (size_t)t * BB * OO;
        const float* nt_t = nonterminals + (size_t)t * BB;

        // h1 = relu([state*nt, a] @ W_sa + b_sa)  [256,1024], K=320
        {
            GemmOp op{st, SS, nt_t, a_t, AA, W_sa, b_sa, h1, HH, 1};
            gemm_kernel<<<dim3(HH / 128, 4, 1), 256>>>(op, op);
        }
        // xg = h1 @ W_x + b_x ; hg = belief @ W_h + b_h  [256,3072] each, batched
        {
            GemmOp oa{h1,  HH, nullptr, nullptr, 0, W_x, b_x, xg, 3 * HH, 0};
            GemmOp ob{bel, HH, nullptr, nullptr, 0, W_h, b_h, hg, 3 * HH, 0};
            gemm_kernel<<<dim3(3 * HH / 128, 4, 2), 256>>>(oa, ob);
        }
        // GRU -> new belief
        gru_kernel<<<(BB * HH) / 256, 256>>>(out + O_BEL + (size_t)t * BB * HH);
        // p1 = relu(bel @ W_bp) ; q1 = relu([bel, o] @ W_bq)  batched
        {
            GemmOp oa{bel, HH, nullptr, nullptr, 0, W_bp, b_bp, p1, HH, 1};
            GemmOp ob{bel, HH, nullptr, o_t,    OO, W_bq, b_bq, q1, HH, 1};
            gemm_kernel<<<dim3(HH / 128, 4, 2), 256>>>(oa, ob);
        }
        // ph = p1 @ W_sp ; qh = q1 @ W_sq  [256,512] each, batched
        {
            GemmOp oa{p1, HH, nullptr, nullptr, 0, W_sp, b_sp, ph, 2 * SS, 0};
            GemmOp ob{q1, HH, nullptr, nullptr, 0, W_sq, b_sq, qh, 2 * SS, 0};
            gemm_kernel<<<dim3(2 * SS / 128, 4, 2), 256>>>(oa, ob);
        }
        // sample prior/posterior, write 6 output slices + next state
        heads_kernel<<<(BB * SS) / 256, 256>>>(
            nz + (size_t)t * BB * SS, nz + (size_t)(TT + t) * BB * SS,
            full ? out + O_PRI  + (size_t)t * BB * SS : nullptr,
            full ? out + O_PM   + (size_t)t * BB * SS : nullptr,
            full ? out + O_PS   + (size_t)t * BB * SS : nullptr,
            full ? out + O_POST + (size_t)t * BB * SS : nullptr,
            full ? out + O_QM   + (size_t)t * BB * SS : nullptr,
            full ? out + O_QS   + (size_t)t * BB * SS : nullptr);
    }
}

// round 6
// speedup vs baseline: 2.0194x; 1.3894x over previous
#include <cuda_runtime.h>
#include <cstdint>
#include <math.h>

// Problem dims (fixed by setup_inputs)
#define TT 50
#define BB 256
#define AA 64
#define SS 256
#define HH 1024
#define OO 1024
#define NCTA 296

// ---------------- device scratch (static allocation only) ----------------
__device__ float g_noise[2 * TT * BB * SS];        // 26.2 MB
__device__ float g_qobs[TT * BB * HH];             // 52.4 MB (obs @ W_bq[H:])
__device__ float g_belief[BB * HH];
__device__ float g_state[BB * SS];
__device__ float g_h1[BB * HH];
__device__ float g_xg[BB * 3 * HH];
__device__ float g_hg[BB * 3 * HH];
__device__ float g_p1[BB * HH];
__device__ float g_q1[BB * HH];
__device__ float g_ph[BB * 2 * SS];
__device__ float g_qh[BB * 2 * SS];
__device__ unsigned g_arrive;
__device__ unsigned g_release;

// ---------------- helpers ----------------
__device__ __forceinline__ unsigned long long pack2(float x, float y) {
    unsigned long long r;
    asm("mov.b64 %0, {%1, %2};" : "=l"(r) : "f"(x), "f"(y));
    return r;
}
__device__ __forceinline__ void unpack2(unsigned long long v, float& x, float& y) {
    asm("mov.b64 {%0, %1}, %2;" : "=f"(x), "=f"(y) : "l"(v));
}
__device__ __forceinline__ unsigned long long ffma2(unsigned long long a,
                                                    unsigned long long b,
                                                    unsigned long long c) {
    unsigned long long d;
    asm("fma.rn.f32x2 %0, %1, %2, %3;" : "=l"(d) : "l"(a), "l"(b), "l"(c));
    return d;
}
__device__ __forceinline__ float sigmoidf_(float x) { return 1.0f / (1.0f + expf(-x)); }
__device__ __forceinline__ float softplusf_(float x) {
    return fmaxf(x, 0.0f) + log1pf(expf(-fabsf(x)));
}

// ---------------- grid-wide barrier (persistent kernel) ----------------
__device__ __forceinline__ void grid_bar(unsigned gen) {
    __syncthreads();
    if (threadIdx.x == 0) {
        __threadfence();                       // flush writes + IVALL
        if (atomicAdd(&g_arrive, 1) == gridDim.x - 1) {
            g_arrive = 0;
            __threadfence();
            atomicExch(&g_release, gen);
        } else {
            while (atomicAdd(&g_release, 0) < gen) __nanosleep(64);
            __threadfence();                   // invalidate stale L1
        }
    }
    __syncthreads();
}

// ---------------- JAX threefry2x32 noise (key = (0,42)) ----------------
__device__ __forceinline__ uint32_t rotl32(uint32_t x, int r) {
    return (x << r) | (x >> (32 - r));
}
__device__ __forceinline__ float normal_from_bits(uint32_t bits) {
    uint32_t fb = (bits >> 9) | 0x3f800000u;
    float f = __uint_as_float(fb) - 1.0f;
    const float lo = -0.99999994f;
    float u = f * 2.0f + lo;
    u = fmaxf(lo, u);
    float w = -log1pf(-u * u);
    float p;
    if (w < 5.0f) {
        w -= 2.5f;
        p = 2.81022636e-08f;
        p = fmaf(p, w, 3.43273939e-07f);
        p = fmaf(p, w, -3.5233877e-06f);
        p = fmaf(p, w, -4.39150654e-06f);
        p = fmaf(p, w, 0.00021858087f);
        p = fmaf(p, w, -0.00125372503f);
        p = fmaf(p, w, -0.00417768164f);
        p = fmaf(p, w, 0.246640727f);
        p = fmaf(p, w, 1.50140941f);
    } else {
        w = sqrtf(w) - 3.0f;
        p = -0.000200214257f;
        p = fmaf(p, w, 0.000100950558f);
        p = fmaf(p, w, 0.00134934322f);
        p = fmaf(p, w, -0.00367342844f);
        p = fmaf(p, w, 0.00573950773f);
        p = fmaf(p, w, -0.0076224613f);
        p = fmaf(p, w, 0.00943887047f);
        p = fmaf(p, w, 1.00167406f);
        p = fmaf(p, w, 2.83297682f);
    }
    return 1.41421356f * (p * u);
}

__global__ void noise_kernel() {
    const int total = 2 * TT * BB * SS;
    int i = blockIdx.x * blockDim.x + threadIdx.x;
    if (i >= total) return;
    const uint32_t k0 = 0u, k1 = 42u;
    const uint32_t k2 = k0 ^ k1 ^ 0x1BD11BDAu;
    uint32_t x0 = 0u;
    uint32_t x1 = (uint32_t)i;
    x0 += k0; x1 += k1;
#define RND(r) { x0 += x1; x1 = rotl32(x1, r); x1 ^= x0; }
    RND(13) RND(15) RND(26) RND(6)   x0 += k1; x1 += k2 + 1u;
    RND(17) RND(29) RND(16) RND(24)  x0 += k2; x1 += k0 + 2u;
    RND(13) RND(15) RND(26) RND(6)   x0 += k0; x1 += k1 + 3u;
    RND(17) RND(29) RND(16) RND(24)  x0 += k1; x1 += k2 + 4u;
    RND(13) RND(15) RND(26) RND(6)   x0 += k2; x1 += k0 + 5u;
#undef RND
    g_noise[i] = normal_from_bits(x0 ^ x1);
}

__global__ void init_kernel(const float* __restrict__ prev_state,
                            const float* __restrict__ prev_belief) {
    int i = blockIdx.x * blockDim.x + threadIdx.x;
    if (i == 0) { g_arrive = 0; g_release = 0; }
    if (i < BB * SS) g_state[i] = prev_state[i];
    if (i < BB * HH) g_belief[i] = prev_belief[i];
}

// ---------------- GEMM tile (FFMA2, 64x128, double-buffered) ----------------
struct TileOp {
    const float* A0; int K0;
    const float* rowscale;          // optional per-row scale on A0
    const float* A1; int K1;        // optional concat block
    const float* W;                 // [K, N] row-major
    const float* bias;              // [N] or null
    const float* addsrc;            // optional [M, N] addend (pre-activation)
    float* C;                       // [M, N]
    int N;
    int relu;
};

__device__ void gemm_tile(const TileOp op, int m0, int n0,
                          float As[2][16][64], float Ws[2][16][128]) {
    __syncthreads();                 // smem reuse guard
    const int t = threadIdx.x;
    const int tx = t & 15, ty = t >> 4;
    const int K = op.K0 + op.K1;
    const int nchunks = K >> 4;

    const int am = t >> 2;
    const int ak = (t & 3) << 2;
    const int gm = m0 + am;
    const float rs = op.rowscale ? op.rowscale[gm] : 1.0f;
    const int wk0 = t >> 5;
    const int wn0 = (t & 31) << 2;
    const int wk1 = (t + 256) >> 5;

    unsigned long long acc[4][4];
#pragma unroll
    for (int i = 0; i < 4; ++i)
#pragma unroll
        for (int j = 0; j < 4; ++j) acc[i][j] = 0ull;

    float4 aReg, wReg0, wReg1;

    auto load_regs = [&](int c) {
        int gk = (c << 4) + ak;
        if (gk < op.K0) {
            aReg = *(const float4*)(op.A0 + (size_t)gm * op.K0 + gk);
            aReg.x *= rs; aReg.y *= rs; aReg.z *= rs; aReg.w *= rs;
        } else {
            aReg = *(const float4*)(op.A1 + (size_t)gm * op.K1 + (gk - op.K0));
        }
        const float* wbase = op.W + (size_t)(c << 4) * op.N + n0;
        wReg0 = *(const float4*)(wbase + (size_t)wk0 * op.N + wn0);
        wReg1 = *(const float4*)(wbase + (size_t)wk1 * op.N + wn0);
    };
    auto sts = [&](int b) {
        As[b][ak + 0][am] = aReg.x;
        As[b][ak + 1][am] = aReg.y;
        As[b][ak + 2][am] = aReg.z;
        As[b][ak + 3][am] = aReg.w;
        *(float4*)&Ws[b][wk0][wn0] = wReg0;
        *(float4*)&Ws[b][wk1][wn0] = wReg1;
    };

    load_regs(0);
    sts(0);
    __syncthreads();

    int buf = 0;
    for (int c = 0; c < nchunks; ++c) {
        const bool has_next = (c + 1 < nchunks);
        if (has_next) load_regs(c + 1);
#pragma unroll
        for (int kk = 0; kk < 16; ++kk) {
            float4 av = *(const float4*)(&As[buf][kk][ty << 2]);
            unsigned long long ap0 = pack2(av.x, av.x);
            unsigned long long ap1 = pack2(av.y, av.y);
            unsigned long long ap2 = pack2(av.z, av.z);
            unsigned long long ap3 = pack2(av.w, av.w);
            const unsigned long long* wr =
                (const unsigned long long*)(&Ws[buf][kk][tx << 3]);
            unsigned long long w0 = wr[0], w1 = wr[1], w2 = wr[2], w3 = wr[3];
            acc[0][0] = ffma2(ap0, w0, acc[0][0]);
            acc[0][1] = ffma2(ap0, w1, acc[0][1]);
            acc[0][2] = ffma2(ap0, w2, acc[0][2]);
            acc[0][3] = ffma2(ap0, w3, acc[0][3]);
            acc[1][0] = ffma2(ap1, w0, acc[1][0]);
            acc[1][1] = ffma2(ap1, w1, acc[1][1]);
            acc[1][2] = ffma2(ap1, w2, acc[1][2]);
            acc[1][3] = ffma2(ap1, w3, acc[1][3]);
            acc[2][0] = ffma2(ap2, w0, acc[2][0]);
            acc[2][1] = ffma2(ap2, w1, acc[2][1]);
            acc[2][2] = ffma2(ap2, w2, acc[2][2]);
            acc[2][3] = ffma2(ap2, w3, acc[2][3]);
            acc[3][0] = ffma2(ap3, w0, acc[3][0]);
            acc[3][1] = ffma2(ap3, w1, acc[3][1]);
            acc[3][2] = ffma2(ap3, w2, acc[3][2]);
            acc[3][3] = ffma2(ap3, w3, acc[3][3]);
        }
        if (has_next) {
            sts(buf ^ 1);
            __syncthreads();
            buf ^= 1;
        }
    }

    const int nb = n0 + (tx << 3);
    const int mb = m0 + (ty << 2);
    float bs[8];
#pragma unroll
    for (int c = 0; c < 8; ++c) bs[c] = op.bias ? op.bias[nb + c] : 0.0f;
#pragma unroll
    for (int i = 0; i < 4; ++i) {
        float o[8];
#pragma unroll
        for (int j = 0; j < 4; ++j) unpack2(acc[i][j], o[2 * j], o[2 * j + 1]);
        if (op.addsrc) {
            const float* ar = op.addsrc + (size_t)(mb + i) * op.N + nb;
#pragma unroll
            for (int c = 0; c < 8; ++c) o[c] += ar[c];
        }
#pragma unroll
        for (int c = 0; c < 8; ++c) {
            o[c] += bs[c];
            if (op.relu) o[c] = fmaxf(o[c], 0.0f);
        }
        float4* dst = (float4*)(op.C + (size_t)(mb + i) * op.N + nb);
        dst[0] = make_float4(o[0], o[1], o[2], o[3]);
        dst[1] = make_float4(o[4], o[5], o[6], o[7]);
    }
}

// One-tile-per-CTA launcher (used for the qobs precompute)
__global__ __launch_bounds__(256) void gemm_big(TileOp op) {
    __shared__ float As[2][16][64];
    __shared__ float Ws[2][16][128];
    gemm_tile(op, blockIdx.y * 64, blockIdx.x * 128, As, Ws);
}

// ---------------- persistent whole-scan kernel ----------------
__global__ __launch_bounds__(256, 2) void rssm_kernel(
    const float* __restrict__ actions, const float* __restrict__ observations,
    const float* __restrict__ nonterminals,
    const float* __restrict__ W_sa, const float* __restrict__ b_sa,
    const float* __restrict__ W_x,  const float* __restrict__ W_h,
    const float* __restrict__ b_x,  const float* __restrict__ b_h,
    const float* __restrict__ W_bp, const float* __restrict__ b_bp,
    const float* __restrict__ W_sp, const float* __restrict__ b_sp,
    const float* __restrict__ W_bq, const float* __restrict__ b_bq,
    const float* __restrict__ W_sq, const float* __restrict__ b_sq,
    float* __restrict__ out, int full)
{
    __shared__ float As[2][16][64];
    __shared__ float Ws[2][16][128];
    const int bid = blockIdx.x;
    const int stride = gridDim.x;
    const int tid = threadIdx.x;
    unsigned gen = 0;

    const size_t O_BEL  = 0;
    const size_t O_PRI  = (size_t)TT * BB * HH;
    const size_t O_PM   = O_PRI  + (size_t)TT * BB * SS;
    const size_t O_PS   = O_PM   + (size_t)TT * BB * SS;
    const size_t O_POST = O_PS   + (size_t)TT * BB * SS;
    const size_t O_QM   = O_POST + (size_t)TT * BB * SS;
    const size_t O_QS   = O_QM   + (size_t)TT * BB * SS;

    for (int t = 0; t < TT; ++t) {
        const float* a_t  = actions + (size_t)t * BB * AA;
        const float* nt_t = nonterminals + (size_t)t * BB;
        const float* qo_t = g_qobs + (size_t)t * BB * HH;

        // Phase A: hg = belief @ W_h + b_h (96 tiles) ; h1 = relu([st*nt|a]@W_sa+b_sa) (32)
        for (int tile = bid; tile < 128; tile += stride) {
            if (tile < 96) {
                TileOp op{g_belief, HH, nullptr, nullptr, 0, W_h, b_h, nullptr,
                          g_hg, 3 * HH, 0};
                gemm_tile(op, (tile & 3) * 64, (tile >> 2) * 128, As, Ws);
            } else {
                int r = tile - 96;
                TileOp op{g_state, SS, nt_t, a_t, AA, W_sa, b_sa, nullptr,
                          g_h1, HH, 1};
                gemm_tile(op, (r & 3) * 64, (r >> 2) * 128, As, Ws);
            }
        }
        grid_bar(++gen);

        // Phase B: xg = h1 @ W_x + b_x (96 tiles)
        for (int tile = bid; tile < 96; tile += stride) {
            TileOp op{g_h1, HH, nullptr, nullptr, 0, W_x, b_x, nullptr,
                      g_xg, 3 * HH, 0};
            gemm_tile(op, (tile & 3) * 64, (tile >> 2) * 128, As, Ws);
        }
        grid_bar(++gen);

        // Phase C: GRU elementwise -> belief (+ output)
        {
            float* ob = out + O_BEL + (size_t)t * BB * HH;
            for (int idx = bid * 256 + tid; idx < BB * HH; idx += stride * 256) {
                int b = idx >> 10, j = idx & 1023;
                const float* xr_ = g_xg + (size_t)b * 3072;
                const float* hr_ = g_hg + (size_t)b * 3072;
                float z = sigmoidf_(xr_[j] + hr_[j]);
                float r = sigmoidf_(xr_[1024 + j] + hr_[1024 + j]);
                float cand = tanhf(xr_[2048 + j] + r * hr_[2048 + j]);
                float bo = g_belief[idx];
                float bn = z * bo + (1.0f - z) * cand;
                g_belief[idx] = bn;
                ob[idx] = bn;
            }
        }
        grid_bar(++gen);

        // Phase D: p1 = relu(bel@W_bp+b) (32) ; q1 = relu(bel@W_bq[:H] + qobs + b) (32)
        for (int tile = bid; tile < 64; tile += stride) {
            if (tile < 32) {
                TileOp op{g_belief, HH, nullptr, nullptr, 0, W_bp, b_bp, nullptr,
                          g_p1, HH, 1};
                gemm_tile(op, (tile & 3) * 64, (tile >> 2) * 128, As, Ws);
            } else {
                int r = tile - 32;
                TileOp op{g_belief, HH, nullptr, nullptr, 0, W_bq, b_bq, qo_t,
                          g_q1, HH, 1};
                gemm_tile(op, (r & 3) * 64, (r >> 2) * 128, As, Ws);
            }
        }
        grid_bar(++gen);

        // Phase E: ph = p1 @ W_sp + b_sp (16) ; qh = q1 @ W_sq + b_sq (16)
        for (int tile = bid; tile < 32; tile += stride) {
            if (tile < 16) {
                TileOp op{g_p1, HH, nullptr, nullptr, 0, W_sp, b_sp, nullptr,
                          g_ph, 2 * SS, 0};
                gemm_tile(op, (tile & 3) * 64, (tile >> 2) * 128, As, Ws);
            } else {
                int r = tile - 16;
                TileOp op{g_q1, HH, nullptr, nullptr, 0, W_sq, b_sq, nullptr,
                          g_qh, 2 * SS, 0};
                gemm_tile(op, (r & 3) * 64, (r >> 2) * 128, As, Ws);
            }
        }
        grid_bar(++gen);

        // Phase F: heads elementwise -> outputs + next state
        {
            const float* nP = g_noise + (size_t)t * BB * SS;
            const float* nQ = g_noise + (size_t)(TT + t) * BB * SS;
            for (int idx = bid * 256 + tid; idx < BB * SS; idx += stride * 256) {
                int b = idx >> 8, s = idx & 255;
                float pm = g_ph[b * 512 + s];
                float ps = softplusf_(g_ph[b * 512 + 256 + s]) + 0.1f;
                float pr = pm + ps * nP[idx];
                float qm = g_qh[b * 512 + s];
                float qs = softplusf_(g_qh[b * 512 + 256 + s]) + 0.1f;
                float po = qm + qs * nQ[idx];
                if (full) {
                    size_t o = (size_t)t * BB * SS + idx;
                    out[O_PM + o] = pm;  out[O_PS + o] = ps; out[O_PRI + o]  = pr;
                    out[O_QM + o] = qm;  out[O_QS + o] = qs; out[O_POST + o] = po;
                }
                g_state[idx] = po;
            }
        }
        grid_bar(++gen);
    }
}

// ---------------- launch ----------------
extern "C" void kernel_launch(void* const* d_in, const int* in_sizes, int n_in,
                              void* d_out, int out_size) {
    const float* actions      = (const float*)d_in[0];
    const float* prev_state   = (const float*)d_in[1];
    const float* prev_belief  = (const float*)d_in[2];
    const float* observations = (const float*)d_in[3];
    const float* nonterminals = (const float*)d_in[4];
    const float* W_sa = (const float*)d_in[5];
    const float* b_sa = (const float*)d_in[6];
    const float* W_x  = (const float*)d_in[7];
    const float* W_h  = (const float*)d_in[8];
    const float* b_x  = (const float*)d_in[9];
    const float* b_h  = (const float*)d_in[10];
    const float* W_bp = (const float*)d_in[11];
    const float* b_bp = (const float*)d_in[12];
    const float* W_sp = (const float*)d_in[13];
    const float* b_sp = (const float*)d_in[14];
    const float* W_bq = (const float*)d_in[15];
    const float* b_bq = (const float*)d_in[16];
    const float* W_sq = (const float*)d_in[17];
    const float* b_sq = (const float*)d_in[18];
    float* out = (float*)d_out;

    const size_t FULL = (size_t)TT * BB * (HH + 6 * SS);
    const int full = (size_t)out_size >= FULL;

    float* qobs;
    cudaGetSymbolAddress((void**)&qobs, g_qobs);

    noise_kernel<<<(2 * TT * BB * SS + 255) / 256, 256>>>();
    init_kernel<<<(BB * HH + 255) / 256, 256>>>(prev_state, prev_belief);

    // qobs[t] = obs[t] @ W_bq[H:, :]   ([12800,1024] @ [1024,1024])
    {
        TileOp op{observations, OO, nullptr, nullptr, 0,
                  W_bq + (size_t)HH * HH, nullptr, nullptr, qobs, HH, 0};
        gemm_big<<<dim3(HH / 128, (TT * BB) / 64), 256>>>(op);
    }

    rssm_kernel<<<NCTA, 256>>>(actions, observations, nonterminals,
                               W_sa, b_sa, W_x, W_h, b_x, b_h,
                               W_bp, b_bp, W_sp, b_sp,
                               W_bq, b_bq, W_sq, b_sq, out, full);
}

// round 7
// speedup vs baseline: 2.9727x; 1.4720x over previous
#include <cuda_runtime.h>
#include <cstdint>
#include <math.h>

// Problem dims (fixed by setup_inputs)
#define TT 50
#define BB 256
#define AA 64
#define SS 256
#define HH 1024
#define OO 1024
#define NCTA 296
#define B3H (BB * 3 * HH)
#define BH  (BB * HH)
#define B2S (BB * 2 * SS)

// ---------------- device scratch (static allocation only) ----------------
__device__ float g_noise[2 * TT * BB * SS];        // 26 MB
__device__ float g_qobs[TT * BB * HH];             // 52 MB; reused as p1_all post-scan
__device__ float g_phall[TT * BB * 2 * SS];        // 26 MB (ph_all post-scan)
__device__ float g_belief[BH];
__device__ float g_state[BB * SS];
__device__ float g_h1[BH];
__device__ float g_hg4[4 * B3H];                   // 50 MB (hg K-split partials)
__device__ float g_xg4[4 * B3H];                   // 50 MB
__device__ float g_q18[8 * BH];                    // 8.4 MB
__device__ float g_qh8[8 * B2S];                   // 4.2 MB
__device__ unsigned g_arrive;
__device__ unsigned g_release;
__device__ unsigned g_ticket;

// ---------------- helpers ----------------
__device__ __forceinline__ unsigned long long pack2(float x, float y) {
    unsigned long long r;
    asm("mov.b64 %0, {%1, %2};" : "=l"(r) : "f"(x), "f"(y));
    return r;
}
__device__ __forceinline__ void unpack2(unsigned long long v, float& x, float& y) {
    asm("mov.b64 {%0, %1}, %2;" : "=f"(x), "=f"(y) : "l"(v));
}
__device__ __forceinline__ unsigned long long ffma2(unsigned long long a,
                                                    unsigned long long b,
                                                    unsigned long long c) {
    unsigned long long d;
    asm("fma.rn.f32x2 %0, %1, %2, %3;" : "=l"(d) : "l"(a), "l"(b), "l"(c));
    return d;
}
__device__ __forceinline__ float sigmoidf_(float x) { return 1.0f / (1.0f + expf(-x)); }
__device__ __forceinline__ float softplusf_(float x) {
    return fmaxf(x, 0.0f) + log1pf(expf(-fabsf(x)));
}

// ---------------- grid-wide barrier + ticket reset ----------------
__device__ __forceinline__ void grid_bar(unsigned gen) {
    __syncthreads();
    if (threadIdx.x == 0) {
        __threadfence();
        if (atomicAdd(&g_arrive, 1) == gridDim.x - 1) {
            g_arrive = 0;
            g_ticket = 0;                      // fresh tickets for next phase
            __threadfence();
            atomicExch(&g_release, gen);
        } else {
            while (atomicAdd(&g_release, 0) < gen) __nanosleep(64);
            __threadfence();                   // invalidate stale L1
        }
    }
    __syncthreads();
}

// ---------------- JAX threefry2x32 noise (key = (0,42)) ----------------
__device__ __forceinline__ uint32_t rotl32(uint32_t x, int r) {
    return (x << r) | (x >> (32 - r));
}
__device__ __forceinline__ float normal_from_bits(uint32_t bits) {
    uint32_t fb = (bits >> 9) | 0x3f800000u;
    float f = __uint_as_float(fb) - 1.0f;
    const float lo = -0.99999994f;
    float u = f * 2.0f + lo;
    u = fmaxf(lo, u);
    float w = -log1pf(-u * u);
    float p;
    if (w < 5.0f) {
        w -= 2.5f;
        p = 2.81022636e-08f;
        p = fmaf(p, w, 3.43273939e-07f);
        p = fmaf(p, w, -3.5233877e-06f);
        p = fmaf(p, w, -4.39150654e-06f);
        p = fmaf(p, w, 0.00021858087f);
        p = fmaf(p, w, -0.00125372503f);
        p = fmaf(p, w, -0.00417768164f);
        p = fmaf(p, w, 0.246640727f);
        p = fmaf(p, w, 1.50140941f);
    } else {
        w = sqrtf(w) - 3.0f;
        p = -0.000200214257f;
        p = fmaf(p, w, 0.000100950558f);
        p = fmaf(p, w, 0.00134934322f);
        p = fmaf(p, w, -0.00367342844f);
        p = fmaf(p, w, 0.00573950773f);
        p = fmaf(p, w, -0.0076224613f);
        p = fmaf(p, w, 0.00943887047f);
        p = fmaf(p, w, 1.00167406f);
        p = fmaf(p, w, 2.83297682f);
    }
    return 1.41421356f * (p * u);
}

__global__ void noise_kernel() {
    const int total = 2 * TT * BB * SS;
    int i = blockIdx.x * blockDim.x + threadIdx.x;
    if (i >= total) return;
    const uint32_t k0 = 0u, k1 = 42u;
    const uint32_t k2 = k0 ^ k1 ^ 0x1BD11BDAu;
    uint32_t x0 = 0u;
    uint32_t x1 = (uint32_t)i;
    x0 += k0; x1 += k1;
#define RND(r) { x0 += x1; x1 = rotl32(x1, r); x1 ^= x0; }
    RND(13) RND(15) RND(26) RND(6)   x0 += k1; x1 += k2 + 1u;
    RND(17) RND(29) RND(16) RND(24)  x0 += k2; x1 += k0 + 2u;
    RND(13) RND(15) RND(26) RND(6)   x0 += k0; x1 += k1 + 3u;
    RND(17) RND(29) RND(16) RND(24)  x0 += k1; x1 += k2 + 4u;
    RND(13) RND(15) RND(26) RND(6)   x0 += k2; x1 += k0 + 5u;
#undef RND
    g_noise[i] = normal_from_bits(x0 ^ x1);
}

__global__ void init_kernel(const float* __restrict__ prev_state,
                            const float* __restrict__ prev_belief) {
    int i = blockIdx.x * blockDim.x + threadIdx.x;
    if (i == 0) { g_arrive = 0; g_release = 0; g_ticket = 0; }
    if (i < BB * SS) g_state[i] = prev_state[i];
    if (i < BB * HH) g_belief[i] = prev_belief[i];
}

// ---------------- generic GEMM tile (FFMA2, 64x128, double-buffered) -------
// C_tile[64,128] (+=partial) = act( A_eff[64,K] @ W[K,128] + bias )
// A_eff[m][k] = reluA?( sum_{j<nSum} A0[j*sumStride + m*lda + k] (+Aextra) (+Acb[k]) ) * rowscale[m]
// Concat: k >= K0 reads A1[m*K1 + (k-K0)] (h1 only; no composition there).
struct TileOp {
    const float* A0; int lda; int K0;
    int nSum; size_t sumStride;
    const float* Aextra;            // optional extra matrix summand (same lda)
    const float* Acb;               // optional per-k bias on A
    int reluA;
    const float* rowscale;
    const float* A1; int K1;        // optional concat block, row stride K1
    const float* W;                 // [K, N] row-major (pre-offset for K-split)
    const float* bias;              // [N] or null
    float* C; int N;
    int relu;
};

__device__ void gemm_tile(const TileOp op, int m0, int n0,
                          float As[2][16][64], float Ws[2][16][128]) {
    __syncthreads();                 // smem reuse guard
    const int t = threadIdx.x;
    const int tx = t & 15, ty = t >> 4;
    const int K = op.K0 + op.K1;
    const int nchunks = K >> 4;

    const int am = t >> 2;
    const int ak = (t & 3) << 2;
    const int gm = m0 + am;
    const float rs = op.rowscale ? op.rowscale[gm] : 1.0f;
    const int wk0 = t >> 5;
    const int wn0 = (t & 31) << 2;
    const int wk1 = (t + 256) >> 5;

    unsigned long long acc[4][4];
#pragma unroll
    for (int i = 0; i < 4; ++i)
#pragma unroll
        for (int j = 0; j < 4; ++j) acc[i][j] = 0ull;

    float4 aReg, wReg0, wReg1;

    auto load_regs = [&](int c) {
        int gk = (c << 4) + ak;
        if (gk < op.K0) {
            const float* a = op.A0 + (size_t)gm * op.lda + gk;
            float4 v = *(const float4*)a;
            for (int j = 1; j < op.nSum; ++j) {
                const float4 e = *(const float4*)(a + (size_t)j * op.sumStride);
                v.x += e.x; v.y += e.y; v.z += e.z; v.w += e.w;
            }
            if (op.Aextra) {
                const float4 e = *(const float4*)(op.Aextra + (size_t)gm * op.lda + gk);
                v.x += e.x; v.y += e.y; v.z += e.z; v.w += e.w;
            }
            if (op.Acb) {
                const float4 e = *(const float4*)(op.Acb + gk);
                v.x += e.x; v.y += e.y; v.z += e.z; v.w += e.w;
            }
            if (op.reluA) {
                v.x = fmaxf(v.x, 0.0f); v.y = fmaxf(v.y, 0.0f);
                v.z = fmaxf(v.z, 0.0f); v.w = fmaxf(v.w, 0.0f);
            }
            v.x *= rs; v.y *= rs; v.z *= rs; v.w *= rs;
            aReg = v;
        } else {
            aReg = *(const float4*)(op.A1 + (size_t)gm * op.K1 + (gk - op.K0));
        }
        const float* wbase = op.W + (size_t)(c << 4) * op.N + n0;
        wReg0 = *(const float4*)(wbase + (size_t)wk0 * op.N + wn0);
        wReg1 = *(const float4*)(wbase + (size_t)wk1 * op.N + wn0);
    };
    auto sts = [&](int b) {
        As[b][ak + 0][am] = aReg.x;
        As[b][ak + 1][am] = aReg.y;
        As[b][ak + 2][am] = aReg.z;
        As[b][ak + 3][am] = aReg.w;
        *(float4*)&Ws[b][wk0][wn0] = wReg0;
        *(float4*)&Ws[b][wk1][wn0] = wReg1;
    };

    load_regs(0);
    sts(0);
    __syncthreads();

    int buf = 0;
    for (int c = 0; c < nchunks; ++c) {
        const bool has_next = (c + 1 < nchunks);
        if (has_next) load_regs(c + 1);
#pragma unroll
        for (int kk = 0; kk < 16; ++kk) {
            float4 av = *(const float4*)(&As[buf][kk][ty << 2]);
            unsigned long long ap0 = pack2(av.x, av.x);
            unsigned long long ap1 = pack2(av.y, av.y);
            unsigned long long ap2 = pack2(av.z, av.z);
            unsigned long long ap3 = pack2(av.w, av.w);
            const unsigned long long* wr =
                (const unsigned long long*)(&Ws[buf][kk][tx << 3]);
            unsigned long long w0 = wr[0], w1 = wr[1], w2 = wr[2], w3 = wr[3];
            acc[0][0] = ffma2(ap0, w0, acc[0][0]);
            acc[0][1] = ffma2(ap0, w1, acc[0][1]);
            acc[0][2] = ffma2(ap0, w2, acc[0][2]);
            acc[0][3] = ffma2(ap0, w3, acc[0][3]);
            acc[1][0] = ffma2(ap1, w0, acc[1][0]);
            acc[1][1] = ffma2(ap1, w1, acc[1][1]);
            acc[1][2] = ffma2(ap1, w2, acc[1][2]);
            acc[1][3] = ffma2(ap1, w3, acc[1][3]);
            acc[2][0] = ffma2(ap2, w0, acc[2][0]);
            acc[2][1] = ffma2(ap2, w1, acc[2][1]);
            acc[2][2] = ffma2(ap2, w2, acc[2][2]);
            acc[2][3] = ffma2(ap2, w3, acc[2][3]);
            acc[3][0] = ffma2(ap3, w0, acc[3][0]);
            acc[3][1] = ffma2(ap3, w1, acc[3][1]);
            acc[3][2] = ffma2(ap3, w2, acc[3][2]);
            acc[3][3] = ffma2(ap3, w3, acc[3][3]);
        }
        if (has_next) {
            sts(buf ^ 1);
            __syncthreads();
            buf ^= 1;
        }
    }

    const int nb = n0 + (tx << 3);
    const int mb = m0 + (ty << 2);
    float bs[8];
#pragma unroll
    for (int c = 0; c < 8; ++c) bs[c] = op.bias ? op.bias[nb + c] : 0.0f;
#pragma unroll
    for (int i = 0; i < 4; ++i) {
        float o[8];
#pragma unroll
        for (int j = 0; j < 4; ++j) unpack2(acc[i][j], o[2 * j], o[2 * j + 1]);
#pragma unroll
        for (int c = 0; c < 8; ++c) {
            o[c] += bs[c];
            if (op.relu) o[c] = fmaxf(o[c], 0.0f);
        }
        float4* dst = (float4*)(op.C + (size_t)(mb + i) * op.N + nb);
        dst[0] = make_float4(o[0], o[1], o[2], o[3]);
        dst[1] = make_float4(o[4], o[5], o[6], o[7]);
    }
}

// Static-grid tile launcher (pre/post big GEMMs)
__global__ __launch_bounds__(256) void gemm_big(TileOp op) {
    __shared__ float As[2][16][64];
    __shared__ float Ws[2][16][128];
    gemm_tile(op, blockIdx.y * 64, blockIdx.x * 128, As, Ws);
}

// ---------------- persistent scan kernel (posterior critical path) ---------
__global__ __launch_bounds__(256, 2) void rssm_kernel(
    const float* __restrict__ actions,
    const float* __restrict__ nonterminals,
    const float* __restrict__ W_sa, const float* __restrict__ b_sa,
    const float* __restrict__ W_x,  const float* __restrict__ W_h,
    const float* __restrict__ b_x,  const float* __restrict__ b_h,
    const float* __restrict__ W_bq, const float* __restrict__ b_bq,
    const float* __restrict__ W_sq, const float* __restrict__ b_sq,
    float* __restrict__ out, int full)
{
    __shared__ float As[2][16][64];
    __shared__ float Ws[2][16][128];
    __shared__ unsigned sPiece;
    const int bid = blockIdx.x;
    const int stride = gridDim.x;
    const int tid = threadIdx.x;
    unsigned gen = 0;

    const size_t O_BEL  = 0;
    const size_t O_POST = (size_t)TT * BB * HH + 3 * (size_t)TT * BB * SS;
    const size_t O_QM   = O_POST + (size_t)TT * BB * SS;
    const size_t O_QS   = O_QM   + (size_t)TT * BB * SS;

    auto grab = [&]() -> unsigned {
        __syncthreads();
        if (tid == 0) sPiece = atomicAdd(&g_ticket, 1);
        __syncthreads();
        return sPiece;
    };

    for (int t = 0; t < TT; ++t) {
        const float* a_t  = actions + (size_t)t * BB * AA;
        const float* nt_t = nonterminals + (size_t)t * BB;
        const float* qo_t = g_qobs + (size_t)t * BB * HH;

        // Phase A: h1 (32 pieces) + hg K-split4 (384 pieces)
        for (unsigned p = grab(); p < 416; p = grab()) {
            if (p < 32) {
                TileOp op{g_state, SS, SS, 1, 0, nullptr, nullptr, 0, nt_t,
                          a_t, AA, W_sa, b_sa, g_h1, HH, 1};
                gemm_tile(op, (p & 3) * 64, (p >> 2) * 128, As, Ws);
            } else {
                unsigned q = p - 32;
                int tile = q >> 2, ks = q & 3;
                TileOp op{g_belief + ks * 256, HH, 256, 1, 0, nullptr, nullptr, 0,
                          nullptr, nullptr, 0, W_h + (size_t)ks * 256 * 3 * HH,
                          nullptr, g_hg4 + (size_t)ks * B3H, 3 * HH, 0};
                gemm_tile(op, (tile & 3) * 64, (tile >> 2) * 128, As, Ws);
            }
        }
        grid_bar(++gen);

        // Phase B: xg K-split4 (384 pieces)
        for (unsigned p = grab(); p < 384; p = grab()) {
            int tile = p >> 2, ks = p & 3;
            TileOp op{g_h1 + ks * 256, HH, 256, 1, 0, nullptr, nullptr, 0,
                      nullptr, nullptr, 0, W_x + (size_t)ks * 256 * 3 * HH,
                      nullptr, g_xg4 + (size_t)ks * B3H, 3 * HH, 0};
            gemm_tile(op, (tile & 3) * 64, (tile >> 2) * 128, As, Ws);
        }
        grid_bar(++gen);

        // Phase C: GRU elementwise (sums partials) -> belief (+ output)
        {
            float* ob = out + O_BEL + (size_t)t * BB * HH;
            for (int idx = bid * 256 + tid; idx < BB * HH; idx += stride * 256) {
                int b = idx >> 10, j = idx & 1023;
                size_t base = (size_t)b * 3072 + j;
                float xz = b_x[j], xr = b_x[1024 + j], xh = b_x[2048 + j];
                float hz = b_h[j], hr = b_h[1024 + j], hh = b_h[2048 + j];
#pragma unroll
                for (int jp = 0; jp < 4; ++jp) {
                    const float* xp = g_xg4 + (size_t)jp * B3H + base;
                    const float* hp = g_hg4 + (size_t)jp * B3H + base;
                    xz += xp[0]; xr += xp[1024]; xh += xp[2048];
                    hz += hp[0]; hr += hp[1024]; hh += hp[2048];
                }
                float z = sigmoidf_(xz + hz);
                float r = sigmoidf_(xr + hr);
                float cand = tanhf(xh + r * hh);
                float bo = g_belief[idx];
                float bn = z * bo + (1.0f - z) * cand;
                g_belief[idx] = bn;
                ob[idx] = bn;
            }
        }
        grid_bar(++gen);

        // Phase D: q1 = bel @ W_bq[:H]  K-split8 (256 pieces, partials)
        for (unsigned p = grab(); p < 256; p = grab()) {
            int tile = p >> 3, ks = p & 7;
            TileOp op{g_belief + ks * 128, HH, 128, 1, 0, nullptr, nullptr, 0,
                      nullptr, nullptr, 0, W_bq + (size_t)ks * 128 * HH,
                      nullptr, g_q18 + (size_t)ks * BH, HH, 0};
            gemm_tile(op, (tile & 3) * 64, (tile >> 2) * 128, As, Ws);
        }
        grid_bar(++gen);

        // Phase E: qh = relu(sum q1 + qobs + b_bq) @ W_sq  K-split8 (128 pieces)
        for (unsigned p = grab(); p < 128; p = grab()) {
            int tile = p >> 3, ks = p & 7;
            TileOp op{g_q18 + ks * 128, HH, 128, 8, (size_t)BH, qo_t + ks * 128,
                      b_bq + ks * 128, 1, nullptr, nullptr, 0,
                      W_sq + (size_t)ks * 128 * 2 * SS,
                      nullptr, g_qh8 + (size_t)ks * B2S, 2 * SS, 0};
            gemm_tile(op, (tile & 3) * 64, (tile >> 2) * 128, As, Ws);
        }
        grid_bar(++gen);

        // Phase F: posterior heads (sums qh partials) -> outputs + next state
        {
            const float* nQ = g_noise + (size_t)(TT + t) * BB * SS;
            for (int idx = bid * 256 + tid; idx < BB * SS; idx += stride * 256) {
                int b = idx >> 8, s = idx & 255;
                float qm = b_sq[s], qsr = b_sq[256 + s];
#pragma unroll
                for (int jp = 0; jp < 8; ++jp) {
                    const float* qp = g_qh8 + (size_t)jp * B2S + b * 512 + s;
                    qm += qp[0]; qsr += qp[256];
                }
                float qs = softplusf_(qsr) + 0.1f;
                float po = qm + qs * nQ[idx];
                if (full) {
                    size_t o = (size_t)t * BB * SS + idx;
                    out[O_QM + o] = qm; out[O_QS + o] = qs; out[O_POST + o] = po;
                }
                g_state[idx] = po;
            }
        }
        grid_bar(++gen);
    }
}

// ---------------- prior heads elementwise (post-pass) ----------------
__global__ void prior_heads_kernel(float* __restrict__ out, int full) {
    const size_t O_PRI = (size_t)TT * BB * HH;
    const size_t O_PM  = O_PRI + (size_t)TT * BB * SS;
    const size_t O_PS  = O_PM  + (size_t)TT * BB * SS;
    int idx = blockIdx.x * blockDim.x + threadIdx.x;   // over T*B*S
    if (idx >= TT * BB * SS) return;
    int r = idx >> 8, s = idx & 255;
    float pm = g_phall[(size_t)r * 512 + s];
    float ps = softplusf_(g_phall[(size_t)r * 512 + 256 + s]) + 0.1f;
    float pr = pm + ps * g_noise[idx];
    if (full) { out[O_PM + idx] = pm; out[O_PS + idx] = ps; out[O_PRI + idx] = pr; }
}

// ---------------- launch ----------------
extern "C" void kernel_launch(void* const* d_in, const int* in_sizes, int n_in,
                              void* d_out, int out_size) {
    const float* actions      = (const float*)d_in[0];
    const float* prev_state   = (const float*)d_in[1];
    const float* prev_belief  = (const float*)d_in[2];
    const float* observations = (const float*)d_in[3];
    const float* nonterminals = (const float*)d_in[4];
    const float* W_sa = (const float*)d_in[5];
    const float* b_sa = (const float*)d_in[6];
    const float* W_x  = (const float*)d_in[7];
    const float* W_h  = (const float*)d_in[8];
    const float* b_x  = (const float*)d_in[9];
    const float* b_h  = (const float*)d_in[10];
    const float* W_bp = (const float*)d_in[11];
    const float* b_bp = (const float*)d_in[12];
    const float* W_sp = (const float*)d_in[13];
    const float* b_sp = (const float*)d_in[14];
    const float* W_bq = (const float*)d_in[15];
    const float* b_bq = (const float*)d_in[16];
    const float* W_sq = (const float*)d_in[17];
    const float* b_sq = (const float*)d_in[18];
    float* out = (float*)d_out;

    const size_t FULL = (size_t)TT * BB * (HH + 6 * SS);
    const int full = (size_t)out_size >= FULL;

    float *qobs, *phall;
    cudaGetSymbolAddress((void**)&qobs, g_qobs);
    cudaGetSymbolAddress((void**)&phall, g_phall);

    noise_kernel<<<(2 * TT * BB * SS + 255) / 256, 256>>>();
    init_kernel<<<(BB * HH + 255) / 256, 256>>>(prev_state, prev_belief);

    // Pre: qobs[t] = obs[t] @ W_bq[H:, :]   ([12800,1024] x [1024,1024])
    {
        TileOp op{observations, OO, OO, 1, 0, nullptr, nullptr, 0, nullptr,
                  nullptr, 0, W_bq + (size_t)HH * HH, nullptr, qobs, HH, 0};
        gemm_big<<<dim3(HH / 128, (TT * BB) / 64), 256>>>(op);
    }

    // Scan (posterior critical path only)
    rssm_kernel<<<NCTA, 256>>>(actions, nonterminals,
                               W_sa, b_sa, W_x, W_h, b_x, b_h,
                               W_bq, b_bq, W_sq, b_sq, out, full);

    // Post: prior branch batched over all T
    // p1_all = relu(belief_all @ W_bp + b_bp)   (reuses g_qobs as scratch)
    {
        TileOp op{out /*O_BEL*/, HH, HH, 1, 0, nullptr, nullptr, 0, nullptr,
                  nullptr, 0, W_bp, b_bp, qobs, HH, 1};
        gemm_big<<<dim3(HH / 128, (TT * BB) / 64), 256>>>(op);
    }
    // ph_all = p1_all @ W_sp + b_sp
    {
        TileOp op{qobs, HH, HH, 1, 0, nullptr, nullptr, 0, nullptr,
                  nullptr, 0, W_sp, b_sp, phall, 2 * SS, 0};
        gemm_big<<<dim3(2 * SS / 128, (TT * BB) / 64), 256>>>(op);
    }
    prior_heads_kernel<<<(TT * BB * SS + 255) / 256, 256>>>(out, full);
}